// round 15
// baseline (speedup 1.0000x reference)
#include <cuda_runtime.h>
#include <math.h>
#include <stdint.h>

#define T_TOK 2048
#define HIDDEN 2048
#define NH 32
#define NKV 8
#define HD 128
#define QSIZE (NH*HD)              // 4096
#define KVSIZE (NKV*HD)            // 1024
#define QKVN (QSIZE + 2*KVSIZE)    // 6144
#define WINDOW 512
#define TQ 32
#define AP 136                     // attention smem pitch (floats)

// -------- scratch (device globals: allocation-free) --------
__device__ float g_qkv[T_TOK * QKVN];     // 50.3 MB
__device__ float g_gate[T_TOK * NH];      // 0.26 MB
__device__ float g_attn[T_TOK * QSIZE];   // 33.5 MB

__device__ __forceinline__ float to_tf32(float x)
{
    uint32_t r;
    asm("cvt.rna.tf32.f32 %0, %1;" : "=r"(r) : "f"(x));
    return __uint_as_float(r);
}

__device__ __forceinline__ void mma_tf32(
    float* d, const uint32_t* a, const uint32_t* b)
{
    asm volatile(
        "mma.sync.aligned.m16n8k8.row.col.f32.tf32.tf32.f32 "
        "{%0,%1,%2,%3}, {%4,%5,%6,%7}, {%8,%9}, {%0,%1,%2,%3};\n"
        : "+f"(d[0]), "+f"(d[1]), "+f"(d[2]), "+f"(d[3])
        : "r"(a[0]), "r"(a[1]), "r"(a[2]), "r"(a[3]),
          "r"(b[0]), "r"(b[1]));
}

// =====================================================================
// TF32 tensor-core GEMM with REGISTER-PREFETCH pipelining.
// 128x128 block tile, 8 warps (2x4), warp tile 64x32, k-chunk 16.
// Next tile's LDGs issue BEFORE current tile's mma block -> latency hidden.
// =====================================================================
__global__ __launch_bounds__(256) void gemm_tf32(
    const float* __restrict__ A, const float* __restrict__ B,
    float* __restrict__ C, int M, int N, int K)
{
    __shared__ float As[16][136];
    __shared__ float Bs[16][136];

    const int m0 = blockIdx.y * 128;
    const int n0 = blockIdx.x * 128;
    const int tid  = threadIdx.x;
    const int wid  = tid >> 5;
    const int lane = tid & 31;
    const int wm = (wid >> 2) * 64;
    const int wn = (wid & 3) * 32;
    const int grp = lane >> 2;
    const int tig = lane & 3;

    float acc[4][4][4];
#pragma unroll
    for (int mf = 0; mf < 4; mf++)
#pragma unroll
        for (int nf = 0; nf < 4; nf++)
#pragma unroll
            for (int r = 0; r < 4; r++) acc[mf][nf][r] = 0.f;

    const int am = tid >> 1;
    const int ak = (tid & 1) * 8;
    const int bk = tid >> 4;
    const int bn = (tid & 15) * 8;

    const float* Ap = A + (size_t)(m0 + am) * K + ak;
    const float* Bp = B + (size_t)bk * N + n0 + bn;

    // prologue: load first tile into registers
    float4 av0 = *(const float4*)(Ap);
    float4 av1 = *(const float4*)(Ap + 4);
    float4 bv0 = *(const float4*)(Bp);
    float4 bv1 = *(const float4*)(Bp + 4);

    for (int k0 = 0; k0 < K; k0 += 16) {
        __syncthreads();
        As[ak + 0][am] = to_tf32(av0.x);
        As[ak + 1][am] = to_tf32(av0.y);
        As[ak + 2][am] = to_tf32(av0.z);
        As[ak + 3][am] = to_tf32(av0.w);
        As[ak + 4][am] = to_tf32(av1.x);
        As[ak + 5][am] = to_tf32(av1.y);
        As[ak + 6][am] = to_tf32(av1.z);
        As[ak + 7][am] = to_tf32(av1.w);
        Bs[bk][bn + 0] = to_tf32(bv0.x);
        Bs[bk][bn + 1] = to_tf32(bv0.y);
        Bs[bk][bn + 2] = to_tf32(bv0.z);
        Bs[bk][bn + 3] = to_tf32(bv0.w);
        Bs[bk][bn + 4] = to_tf32(bv1.x);
        Bs[bk][bn + 5] = to_tf32(bv1.y);
        Bs[bk][bn + 6] = to_tf32(bv1.z);
        Bs[bk][bn + 7] = to_tf32(bv1.w);
        __syncthreads();

        // prefetch NEXT tile (latency overlaps the mma block below)
        if (k0 + 16 < K) {
            av0 = *(const float4*)(Ap + k0 + 16);
            av1 = *(const float4*)(Ap + k0 + 20);
            bv0 = *(const float4*)(Bp + (size_t)(k0 + 16) * N);
            bv1 = *(const float4*)(Bp + (size_t)(k0 + 16) * N + 4);
        }

#pragma unroll
        for (int ks = 0; ks < 16; ks += 8) {
            uint32_t af[4][4], bf[4][2];
#pragma unroll
            for (int mf = 0; mf < 4; mf++) {
                int row = wm + mf * 16 + grp;
                af[mf][0] = __float_as_uint(As[ks + tig    ][row]);
                af[mf][1] = __float_as_uint(As[ks + tig    ][row + 8]);
                af[mf][2] = __float_as_uint(As[ks + tig + 4][row]);
                af[mf][3] = __float_as_uint(As[ks + tig + 4][row + 8]);
            }
#pragma unroll
            for (int nf = 0; nf < 4; nf++) {
                int col = wn + nf * 8 + grp;
                bf[nf][0] = __float_as_uint(Bs[ks + tig    ][col]);
                bf[nf][1] = __float_as_uint(Bs[ks + tig + 4][col]);
            }
#pragma unroll
            for (int mf = 0; mf < 4; mf++)
#pragma unroll
                for (int nf = 0; nf < 4; nf++)
                    mma_tf32(acc[mf][nf], af[mf], bf[nf]);
        }
    }

#pragma unroll
    for (int mf = 0; mf < 4; mf++) {
        int row = m0 + wm + mf * 16 + grp;
#pragma unroll
        for (int nf = 0; nf < 4; nf++) {
            int col = n0 + wn + nf * 8 + 2 * tig;
            *(float2*)(C + (size_t)row * N + col) =
                make_float2(acc[mf][nf][0], acc[mf][nf][1]);
            *(float2*)(C + (size_t)(row + 8) * N + col) =
                make_float2(acc[mf][nf][2], acc[mf][nf][3]);
        }
    }
}

// =====================================================================
// RMSNorm + RoPE in place. sincosf(x, &s, &c): sin FIRST.
// =====================================================================
__global__ __launch_bounds__(128) void norm_rope_k(
    const int* __restrict__ pos,
    const float* __restrict__ qw, const float* __restrict__ kw)
{
    const int t  = blockIdx.x;
    const int hh = blockIdx.y;
    const bool is_q = (hh < NH);
    float* x = g_qkv + (size_t)t * QKVN +
               (is_q ? hh * HD : QSIZE + (hh - NH) * HD);
    const float* w = is_q ? qw : kw;
    const int d = threadIdx.x;

    float v = x[d];
    float ss = v * v;
#pragma unroll
    for (int o = 16; o; o >>= 1) ss += __shfl_xor_sync(0xffffffffu, ss, o);
    __shared__ float red[4];
    if ((d & 31) == 0) red[d >> 5] = ss;
    __syncthreads();
    float r = rsqrtf((red[0] + red[1] + red[2] + red[3]) * (1.0f / HD) + 1e-6f);

    __shared__ float xs[HD];
    xs[d] = v * r * w[d];
    __syncthreads();

    if (d < 64) {
        float inv = powf(10000.0f, -(float)(2 * d) * (1.0f / HD));
        float ang = (float)pos[t] * inv;
        float s, c;
        sincosf(ang, &s, &c);
        float x1 = xs[d], x2 = xs[d + 64];
        x[d]      = x1 * c - x2 * s;
        x[d + 64] = x2 * c + x1 * s;
    }
}

// =====================================================================
// Gate: softplus(X @ Wg). grid T, block 256.
// =====================================================================
__global__ __launch_bounds__(256) void gate_k(
    const float* __restrict__ X, const float* __restrict__ wg)
{
    const int t   = blockIdx.x;
    const int h   = threadIdx.x >> 3;
    const int sub = threadIdx.x & 7;
    const float* xr = X + (size_t)t * HIDDEN;

    float acc = 0.f;
    for (int k = sub; k < HIDDEN; k += 8)
        acc = fmaf(xr[k], wg[(size_t)k * NH + h], acc);
    acc += __shfl_xor_sync(0xffffffffu, acc, 1);
    acc += __shfl_xor_sync(0xffffffffu, acc, 2);
    acc += __shfl_xor_sync(0xffffffffu, acc, 4);
    if (sub == 0) {
        float sp = (acc > 20.f) ? acc : log1pf(expf(acc));
        g_gate[(size_t)t * NH + h] = sp;
    }
}

// =====================================================================
// Sliding-window attention with TF32 MMA (unchanged from round 13).
// =====================================================================
#define ATTN_SMEM_FLOATS ((TQ + 128 + TQ) * AP + 3 * TQ)
#define ATTN_SMEM_BYTES  (ATTN_SMEM_FLOATS * 4)

__global__ __launch_bounds__(256) void attn_k()
{
    extern __shared__ float sm[];
    float* qs   = sm;                    // Q  [TQ][AP] (tf32, pre-scaled)
    float* kv   = sm + TQ * AP;          // K or V [128][AP] natural
    float* sc   = kv + 128 * AP;         // scores / P [TQ][AP]
    float* mrow = sc + TQ * AP;
    float* lrow = mrow + TQ;
    float* frow = lrow + TQ;

    const int t0  = blockIdx.x * TQ;
    const int h   = blockIdx.y;
    const int kvh = h >> 2;
    const int tid = threadIdx.x;
    const int wid = tid >> 5;
    const int ln  = tid & 31;
    const int wm  = (wid >> 2) * 16;
    const int wn  = (wid & 3) * 32;
    const int grp = ln >> 2;
    const int tig = ln & 3;

    const int s_min = max(0, t0 - (WINDOW - 1));
    const int s_end = t0 + TQ;
    const float scale = 0.08838834764831845f;

    if (tid < TQ) { mrow[tid] = -1e30f; lrow[tid] = 0.f; }
    for (int i = tid; i < TQ * 32; i += 256) {
        int m = i >> 5, c = (i & 31) * 4;
        float4 v = *(const float4*)(g_qkv + (size_t)(t0 + m) * QKVN + h * HD + c);
        qs[m * AP + c + 0] = to_tf32(v.x * scale);
        qs[m * AP + c + 1] = to_tf32(v.y * scale);
        qs[m * AP + c + 2] = to_tf32(v.z * scale);
        qs[m * AP + c + 3] = to_tf32(v.w * scale);
    }

    float o[4][4];
#pragma unroll
    for (int nf = 0; nf < 4; nf++)
#pragma unroll
        for (int r = 0; r < 4; r++) o[nf][r] = 0.f;

    const int row0 = wm + grp;
    const int row1 = row0 + 8;

    for (int cs = s_min; cs < s_end; cs += 128) {
        const int cn = min(128, s_end - cs);
        __syncthreads();

        for (int i = tid; i < cn * 32; i += 256) {
            int j = i >> 5, c = (i & 31) * 4;
            float4 v = *(const float4*)(g_qkv + (size_t)(cs + j) * QKVN +
                                        QSIZE + kvh * HD + c);
            kv[j * AP + c + 0] = to_tf32(v.x);
            kv[j * AP + c + 1] = to_tf32(v.y);
            kv[j * AP + c + 2] = to_tf32(v.z);
            kv[j * AP + c + 3] = to_tf32(v.w);
        }
        __syncthreads();

        float acc[4][4];
#pragma unroll
        for (int nf = 0; nf < 4; nf++)
#pragma unroll
            for (int r = 0; r < 4; r++) acc[nf][r] = 0.f;

#pragma unroll
        for (int ks = 0; ks < 16; ks++) {
            const int k0 = ks * 8;
            uint32_t a[4];
            a[0] = __float_as_uint(qs[row0 * AP + k0 + tig]);
            a[1] = __float_as_uint(qs[row1 * AP + k0 + tig]);
            a[2] = __float_as_uint(qs[row0 * AP + k0 + tig + 4]);
            a[3] = __float_as_uint(qs[row1 * AP + k0 + tig + 4]);
#pragma unroll
            for (int nf = 0; nf < 4; nf++) {
                const int key = wn + nf * 8 + grp;
                uint32_t b[2];
                b[0] = __float_as_uint(kv[key * AP + k0 + tig]);
                b[1] = __float_as_uint(kv[key * AP + k0 + tig + 4]);
                mma_tf32(acc[nf], a, b);
            }
        }

#pragma unroll
        for (int nf = 0; nf < 4; nf++) {
            const int col = wn + nf * 8 + 2 * tig;
            const int s0 = cs + col, s1 = s0 + 1;
            int d00 = (t0 + row0) - s0, d01 = (t0 + row0) - s1;
            int d10 = (t0 + row1) - s0, d11 = (t0 + row1) - s1;
            sc[row0 * AP + col]     = (d00 >= 0 && d00 < WINDOW) ? acc[nf][0] : -1e30f;
            sc[row0 * AP + col + 1] = (d01 >= 0 && d01 < WINDOW) ? acc[nf][1] : -1e30f;
            sc[row1 * AP + col]     = (d10 >= 0 && d10 < WINDOW) ? acc[nf][2] : -1e30f;
            sc[row1 * AP + col + 1] = (d11 >= 0 && d11 < WINDOW) ? acc[nf][3] : -1e30f;
        }
        __syncthreads();

        for (int r = wid; r < TQ; r += 8) {
            float* row = sc + r * AP;
            float mx = -1e30f;
#pragma unroll 4
            for (int j = ln; j < 128; j += 32) mx = fmaxf(mx, row[j]);
#pragma unroll
            for (int off = 16; off; off >>= 1)
                mx = fmaxf(mx, __shfl_xor_sync(0xffffffffu, mx, off));
            float mold = mrow[r];
            float mnew = fmaxf(mold, mx);
            float f    = expf(mold - mnew);
            float sum  = 0.f;
#pragma unroll 4
            for (int j = ln; j < 128; j += 32) {
                float e = expf(row[j] - mnew);
                row[j] = to_tf32(e);
                sum += e;
            }
#pragma unroll
            for (int off = 16; off; off >>= 1)
                sum += __shfl_xor_sync(0xffffffffu, sum, off);
            if (ln == 0) {
                mrow[r] = mnew;
                lrow[r] = lrow[r] * f + sum;
                frow[r] = f;
            }
        }
        __syncthreads();

        for (int i = tid; i < cn * 32; i += 256) {
            int j = i >> 5, c = (i & 31) * 4;
            float4 v = *(const float4*)(g_qkv + (size_t)(cs + j) * QKVN +
                                        QSIZE + KVSIZE + kvh * HD + c);
            kv[j * AP + c + 0] = to_tf32(v.x);
            kv[j * AP + c + 1] = to_tf32(v.y);
            kv[j * AP + c + 2] = to_tf32(v.z);
            kv[j * AP + c + 3] = to_tf32(v.w);
        }
        for (int i = cn * 32 + tid; i < 128 * 32; i += 256) {
            int j = i >> 5, c = (i & 31) * 4;
            kv[j * AP + c + 0] = 0.f;
            kv[j * AP + c + 1] = 0.f;
            kv[j * AP + c + 2] = 0.f;
            kv[j * AP + c + 3] = 0.f;
        }
        __syncthreads();

        {
            float f0 = frow[row0], f1 = frow[row1];
#pragma unroll
            for (int nf = 0; nf < 4; nf++) {
                o[nf][0] *= f0; o[nf][1] *= f0;
                o[nf][2] *= f1; o[nf][3] *= f1;
            }
        }
#pragma unroll
        for (int ks = 0; ks < 16; ks++) {
            const int k0 = ks * 8;
            uint32_t a[4];
            a[0] = __float_as_uint(sc[row0 * AP + k0 + tig]);
            a[1] = __float_as_uint(sc[row1 * AP + k0 + tig]);
            a[2] = __float_as_uint(sc[row0 * AP + k0 + tig + 4]);
            a[3] = __float_as_uint(sc[row1 * AP + k0 + tig + 4]);
#pragma unroll
            for (int nf = 0; nf < 4; nf++) {
                const int dimc = wn + nf * 8 + grp;
                uint32_t b[2];
                b[0] = __float_as_uint(kv[(k0 + tig)     * AP + dimc]);
                b[1] = __float_as_uint(kv[(k0 + tig + 4) * AP + dimc]);
                mma_tf32(o[nf], a, b);
            }
        }
    }
    __syncthreads();

    {
        float g0 = g_gate[(size_t)(t0 + row0) * NH + h] / lrow[row0];
        float g1 = g_gate[(size_t)(t0 + row1) * NH + h] / lrow[row1];
#pragma unroll
        for (int nf = 0; nf < 4; nf++) {
            const int col = wn + nf * 8 + 2 * tig;
            *(float2*)(g_attn + (size_t)(t0 + row0) * QSIZE + h * HD + col) =
                make_float2(o[nf][0] * g0, o[nf][1] * g0);
            *(float2*)(g_attn + (size_t)(t0 + row1) * QSIZE + h * HD + col) =
                make_float2(o[nf][2] * g1, o[nf][3] * g1);
        }
    }
}

// =====================================================================
// launch
// =====================================================================
extern "C" void kernel_launch(void* const* d_in, const int* in_sizes, int n_in,
                              void* d_out, int out_size)
{
    const int*   positions = 0;
    const float* X    = 0;
    const float* Wqkv = 0;
    const float* Wo   = 0;
    const float* Wg   = 0;
    const float* qw   = 0;
    const float* kw   = 0;

    for (int i = 0; i < n_in; i++) {
        switch (in_sizes[i]) {
            case T_TOK:          positions = (const int*)d_in[i];     break;
            case T_TOK*HIDDEN:   X    = (const float*)d_in[i];        break;
            case HIDDEN*QKVN:    Wqkv = (const float*)d_in[i];        break;
            case QSIZE*HIDDEN:   Wo   = (const float*)d_in[i];        break;
            case HIDDEN*NH:      Wg   = (const float*)d_in[i];        break;
            case HD:             if (!qw) qw = (const float*)d_in[i];
                                 else     kw = (const float*)d_in[i]; break;
            default: break;
        }
    }

    float *qkv_p, *attn_p;
    cudaGetSymbolAddress((void**)&qkv_p,  g_qkv);
    cudaGetSymbolAddress((void**)&attn_p, g_attn);
    float* out = (float*)d_out;

    // 1) QKV GEMM (TF32, pipelined): [2048,2048] x [2048,6144]
    gemm_tf32<<<dim3(QKVN / 128, T_TOK / 128), 256>>>(X, Wqkv, qkv_p,
                                                      T_TOK, QKVN, HIDDEN);
    // 2) RMSNorm + RoPE in place
    norm_rope_k<<<dim3(T_TOK, NH + NKV), 128>>>(positions, qw, kw);
    // 3) Gate
    gate_k<<<T_TOK, 256>>>(X, Wg);
    // 4) Attention (TF32 mma QK + PV, online softmax)
    cudaFuncSetAttribute(attn_k, cudaFuncAttributeMaxDynamicSharedMemorySize,
                         ATTN_SMEM_BYTES);
    attn_k<<<dim3(T_TOK / TQ, NH), 256, ATTN_SMEM_BYTES>>>();
    // 5) Output GEMM (TF32, pipelined): [2048,4096] x [4096,2048]
    gemm_tf32<<<dim3(HIDDEN / 128, T_TOK / 128), 256>>>(attn_p, Wo, out,
                                                        T_TOK, HIDDEN, QSIZE);
    (void)out_size;
}

// round 16
// speedup vs baseline: 1.0811x; 1.0811x over previous
#include <cuda_runtime.h>
#include <math.h>
#include <stdint.h>

#define T_TOK 2048
#define HIDDEN 2048
#define NH 32
#define NKV 8
#define HD 128
#define QSIZE (NH*HD)              // 4096
#define KVSIZE (NKV*HD)            // 1024
#define QKVN (QSIZE + 2*KVSIZE)    // 6144
#define WINDOW 512
#define TQ 32
#define AP 136                     // attention smem pitch (floats)

// -------- scratch (device globals: allocation-free) --------
__device__ float g_qkv[T_TOK * QKVN];       // 50.3 MB
__device__ float g_gate[T_TOK * NH];        // 0.26 MB
__device__ float g_attn[T_TOK * QSIZE];     // 33.5 MB (tf32-rounded)
__device__ float g_xt[T_TOK * HIDDEN];      // 16.8 MB (X, tf32)
__device__ float g_wqkvt[HIDDEN * QKVN];    // 50.3 MB (Wqkv, tf32)
__device__ float g_wot[QSIZE * HIDDEN];     // 33.5 MB (Wo, tf32)

__device__ __forceinline__ float to_tf32(float x)
{
    uint32_t r;
    asm("cvt.rna.tf32.f32 %0, %1;" : "=r"(r) : "f"(x));
    return __uint_as_float(r);
}

__device__ __forceinline__ void mma_tf32(
    float* d, const uint32_t* a, const uint32_t* b)
{
    asm volatile(
        "mma.sync.aligned.m16n8k8.row.col.f32.tf32.tf32.f32 "
        "{%0,%1,%2,%3}, {%4,%5,%6,%7}, {%8,%9}, {%0,%1,%2,%3};\n"
        : "+f"(d[0]), "+f"(d[1]), "+f"(d[2]), "+f"(d[3])
        : "r"(a[0]), "r"(a[1]), "r"(a[2]), "r"(a[3]),
          "r"(b[0]), "r"(b[1]));
}

#define CP16(saddr, gptr) \
    asm volatile("cp.async.ca.shared.global [%0], [%1], 16;\n" \
                 :: "r"(saddr), "l"(gptr) : "memory")
#define CP_COMMIT() asm volatile("cp.async.commit_group;\n" ::: "memory")
#define CP_WAIT1()  asm volatile("cp.async.wait_group 1;\n" ::: "memory")

// =====================================================================
// tf32 pre-conversion: dst[i] = round_rna_tf32(src[i]); n % 4 == 0.
// =====================================================================
__global__ __launch_bounds__(256) void cvt_tf32_k(
    const float* __restrict__ s, float* __restrict__ d, int n)
{
    int i = (blockIdx.x * 256 + threadIdx.x) * 4;
    if (i < n) {
        float4 v = *(const float4*)(s + i);
        v.x = to_tf32(v.x); v.y = to_tf32(v.y);
        v.z = to_tf32(v.z); v.w = to_tf32(v.w);
        *(float4*)(d + i) = v;
    }
}

// =====================================================================
// TF32 GEMM with cp.async DOUBLE-BUFFERED smem pipeline.
// Inputs A, B must already be tf32-rounded. 128x128 tile, 8 warps,
// warp tile 64x32, k-chunk 16, 2 stages.
// A stored natural [m][k] pitch 20; B [k][n] pitch 136 (conflict-free).
// =====================================================================
__global__ __launch_bounds__(256) void gemm_tf32_cp(
    const float* __restrict__ A, const float* __restrict__ B,
    float* __restrict__ C, int M, int N, int K)
{
    __shared__ float As[2][128][20];
    __shared__ float Bs[2][16][136];

    const int m0 = blockIdx.y * 128;
    const int n0 = blockIdx.x * 128;
    const int tid  = threadIdx.x;
    const int wid  = tid >> 5;
    const int lane = tid & 31;
    const int wm = (wid >> 2) * 64;
    const int wn = (wid & 3) * 32;
    const int grp = lane >> 2;
    const int tig = lane & 3;

    float acc[4][4][4];
#pragma unroll
    for (int mf = 0; mf < 4; mf++)
#pragma unroll
        for (int nf = 0; nf < 4; nf++)
#pragma unroll
            for (int r = 0; r < 4; r++) acc[mf][nf][r] = 0.f;

    // per-thread copy slots: A row ar, k cols ac..ac+7; B row br, n cols bc..bc+7
    const int ar = tid >> 1, ac = (tid & 1) * 8;
    const int br = tid >> 4, bc = (tid & 15) * 8;
    const float* gA = A + (size_t)(m0 + ar) * K + ac;
    const float* gB = B + (size_t)br * N + n0 + bc;

    const uint32_t sAme = (uint32_t)__cvta_generic_to_shared(&As[0][ar][ac]);
    const uint32_t sBme = (uint32_t)__cvta_generic_to_shared(&Bs[0][br][bc]);
    const uint32_t ASTG = 128 * 20 * 4;
    const uint32_t BSTG = 16 * 136 * 4;

    const int nt = K / 16;

#define GEMM_ISSUE(tile)                                              \
    do {                                                              \
        const int st_ = (tile) & 1;                                   \
        const float* a_ = gA + (tile) * 16;                           \
        const float* b_ = gB + (size_t)((tile) * 16) * N;             \
        CP16(sAme + st_ * ASTG,      a_);                             \
        CP16(sAme + st_ * ASTG + 16, a_ + 4);                         \
        CP16(sBme + st_ * BSTG,      b_);                             \
        CP16(sBme + st_ * BSTG + 16, b_ + 4);                         \
    } while (0)

    GEMM_ISSUE(0); CP_COMMIT();
    GEMM_ISSUE(1); CP_COMMIT();

    for (int it = 0; it < nt; it++) {
        CP_WAIT1();
        __syncthreads();
        const int st = it & 1;

#pragma unroll
        for (int ks = 0; ks < 16; ks += 8) {
            uint32_t af[4][4], bf[4][2];
#pragma unroll
            for (int mf = 0; mf < 4; mf++) {
                int row = wm + mf * 16 + grp;
                af[mf][0] = __float_as_uint(As[st][row    ][ks + tig]);
                af[mf][1] = __float_as_uint(As[st][row + 8][ks + tig]);
                af[mf][2] = __float_as_uint(As[st][row    ][ks + tig + 4]);
                af[mf][3] = __float_as_uint(As[st][row + 8][ks + tig + 4]);
            }
#pragma unroll
            for (int nf = 0; nf < 4; nf++) {
                int col = wn + nf * 8 + grp;
                bf[nf][0] = __float_as_uint(Bs[st][ks + tig    ][col]);
                bf[nf][1] = __float_as_uint(Bs[st][ks + tig + 4][col]);
            }
#pragma unroll
            for (int mf = 0; mf < 4; mf++)
#pragma unroll
                for (int nf = 0; nf < 4; nf++)
                    mma_tf32(acc[mf][nf], af[mf], bf[nf]);
        }

        __syncthreads();
        if (it + 2 < nt) GEMM_ISSUE(it + 2);
        CP_COMMIT();
    }

#pragma unroll
    for (int mf = 0; mf < 4; mf++) {
        int row = m0 + wm + mf * 16 + grp;
#pragma unroll
        for (int nf = 0; nf < 4; nf++) {
            int col = n0 + wn + nf * 8 + 2 * tig;
            *(float2*)(C + (size_t)row * N + col) =
                make_float2(acc[mf][nf][0], acc[mf][nf][1]);
            *(float2*)(C + (size_t)(row + 8) * N + col) =
                make_float2(acc[mf][nf][2], acc[mf][nf][3]);
        }
    }
#undef GEMM_ISSUE
}

// =====================================================================
// RMSNorm + RoPE in place. sincosf(x, &s, &c): sin FIRST.
// =====================================================================
__global__ __launch_bounds__(128) void norm_rope_k(
    const int* __restrict__ pos,
    const float* __restrict__ qw, const float* __restrict__ kw)
{
    const int t  = blockIdx.x;
    const int hh = blockIdx.y;
    const bool is_q = (hh < NH);
    float* x = g_qkv + (size_t)t * QKVN +
               (is_q ? hh * HD : QSIZE + (hh - NH) * HD);
    const float* w = is_q ? qw : kw;
    const int d = threadIdx.x;

    float v = x[d];
    float ss = v * v;
#pragma unroll
    for (int o = 16; o; o >>= 1) ss += __shfl_xor_sync(0xffffffffu, ss, o);
    __shared__ float red[4];
    if ((d & 31) == 0) red[d >> 5] = ss;
    __syncthreads();
    float r = rsqrtf((red[0] + red[1] + red[2] + red[3]) * (1.0f / HD) + 1e-6f);

    __shared__ float xs[HD];
    xs[d] = v * r * w[d];
    __syncthreads();

    if (d < 64) {
        float inv = powf(10000.0f, -(float)(2 * d) * (1.0f / HD));
        float ang = (float)pos[t] * inv;
        float s, c;
        sincosf(ang, &s, &c);
        float x1 = xs[d], x2 = xs[d + 64];
        x[d]      = x1 * c - x2 * s;
        x[d + 64] = x2 * c + x1 * s;
    }
}

// =====================================================================
// Gate: softplus(X @ Wg). grid T, block 256.
// =====================================================================
__global__ __launch_bounds__(256) void gate_k(
    const float* __restrict__ X, const float* __restrict__ wg)
{
    const int t   = blockIdx.x;
    const int h   = threadIdx.x >> 3;
    const int sub = threadIdx.x & 7;
    const float* xr = X + (size_t)t * HIDDEN;

    float acc = 0.f;
    for (int k = sub; k < HIDDEN; k += 8)
        acc = fmaf(xr[k], wg[(size_t)k * NH + h], acc);
    acc += __shfl_xor_sync(0xffffffffu, acc, 1);
    acc += __shfl_xor_sync(0xffffffffu, acc, 2);
    acc += __shfl_xor_sync(0xffffffffu, acc, 4);
    if (sub == 0) {
        float sp = (acc > 20.f) ? acc : log1pf(expf(acc));
        g_gate[(size_t)t * NH + h] = sp;
    }
}

// =====================================================================
// Sliding-window attention with TF32 MMA (round-13 version; epilogue
// now stores tf32-rounded values so out-proj GEMM needs no cvt).
// =====================================================================
#define ATTN_SMEM_FLOATS ((TQ + 128 + TQ) * AP + 3 * TQ)
#define ATTN_SMEM_BYTES  (ATTN_SMEM_FLOATS * 4)

__global__ __launch_bounds__(256) void attn_k()
{
    extern __shared__ float sm[];
    float* qs   = sm;                    // Q  [TQ][AP] (tf32, pre-scaled)
    float* kv   = sm + TQ * AP;          // K or V [128][AP] natural
    float* sc   = kv + 128 * AP;         // scores / P [TQ][AP]
    float* mrow = sc + TQ * AP;
    float* lrow = mrow + TQ;
    float* frow = lrow + TQ;

    const int t0  = blockIdx.x * TQ;
    const int h   = blockIdx.y;
    const int kvh = h >> 2;
    const int tid = threadIdx.x;
    const int wid = tid >> 5;
    const int ln  = tid & 31;
    const int wm  = (wid >> 2) * 16;
    const int wn  = (wid & 3) * 32;
    const int grp = ln >> 2;
    const int tig = ln & 3;

    const int s_min = max(0, t0 - (WINDOW - 1));
    const int s_end = t0 + TQ;
    const float scale = 0.08838834764831845f;

    if (tid < TQ) { mrow[tid] = -1e30f; lrow[tid] = 0.f; }
    for (int i = tid; i < TQ * 32; i += 256) {
        int m = i >> 5, c = (i & 31) * 4;
        float4 v = *(const float4*)(g_qkv + (size_t)(t0 + m) * QKVN + h * HD + c);
        qs[m * AP + c + 0] = to_tf32(v.x * scale);
        qs[m * AP + c + 1] = to_tf32(v.y * scale);
        qs[m * AP + c + 2] = to_tf32(v.z * scale);
        qs[m * AP + c + 3] = to_tf32(v.w * scale);
    }

    float o[4][4];
#pragma unroll
    for (int nf = 0; nf < 4; nf++)
#pragma unroll
        for (int r = 0; r < 4; r++) o[nf][r] = 0.f;

    const int row0 = wm + grp;
    const int row1 = row0 + 8;

    for (int cs = s_min; cs < s_end; cs += 128) {
        const int cn = min(128, s_end - cs);
        __syncthreads();

        for (int i = tid; i < cn * 32; i += 256) {
            int j = i >> 5, c = (i & 31) * 4;
            float4 v = *(const float4*)(g_qkv + (size_t)(cs + j) * QKVN +
                                        QSIZE + kvh * HD + c);
            kv[j * AP + c + 0] = to_tf32(v.x);
            kv[j * AP + c + 1] = to_tf32(v.y);
            kv[j * AP + c + 2] = to_tf32(v.z);
            kv[j * AP + c + 3] = to_tf32(v.w);
        }
        __syncthreads();

        float acc[4][4];
#pragma unroll
        for (int nf = 0; nf < 4; nf++)
#pragma unroll
            for (int r = 0; r < 4; r++) acc[nf][r] = 0.f;

#pragma unroll
        for (int ks = 0; ks < 16; ks++) {
            const int k0 = ks * 8;
            uint32_t a[4];
            a[0] = __float_as_uint(qs[row0 * AP + k0 + tig]);
            a[1] = __float_as_uint(qs[row1 * AP + k0 + tig]);
            a[2] = __float_as_uint(qs[row0 * AP + k0 + tig + 4]);
            a[3] = __float_as_uint(qs[row1 * AP + k0 + tig + 4]);
#pragma unroll
            for (int nf = 0; nf < 4; nf++) {
                const int key = wn + nf * 8 + grp;
                uint32_t b[2];
                b[0] = __float_as_uint(kv[key * AP + k0 + tig]);
                b[1] = __float_as_uint(kv[key * AP + k0 + tig + 4]);
                mma_tf32(acc[nf], a, b);
            }
        }

#pragma unroll
        for (int nf = 0; nf < 4; nf++) {
            const int col = wn + nf * 8 + 2 * tig;
            const int s0 = cs + col, s1 = s0 + 1;
            int d00 = (t0 + row0) - s0, d01 = (t0 + row0) - s1;
            int d10 = (t0 + row1) - s0, d11 = (t0 + row1) - s1;
            sc[row0 * AP + col]     = (d00 >= 0 && d00 < WINDOW) ? acc[nf][0] : -1e30f;
            sc[row0 * AP + col + 1] = (d01 >= 0 && d01 < WINDOW) ? acc[nf][1] : -1e30f;
            sc[row1 * AP + col]     = (d10 >= 0 && d10 < WINDOW) ? acc[nf][2] : -1e30f;
            sc[row1 * AP + col + 1] = (d11 >= 0 && d11 < WINDOW) ? acc[nf][3] : -1e30f;
        }
        __syncthreads();

        for (int r = wid; r < TQ; r += 8) {
            float* row = sc + r * AP;
            float mx = -1e30f;
#pragma unroll 4
            for (int j = ln; j < 128; j += 32) mx = fmaxf(mx, row[j]);
#pragma unroll
            for (int off = 16; off; off >>= 1)
                mx = fmaxf(mx, __shfl_xor_sync(0xffffffffu, mx, off));
            float mold = mrow[r];
            float mnew = fmaxf(mold, mx);
            float f    = expf(mold - mnew);
            float sum  = 0.f;
#pragma unroll 4
            for (int j = ln; j < 128; j += 32) {
                float e = expf(row[j] - mnew);
                row[j] = to_tf32(e);
                sum += e;
            }
#pragma unroll
            for (int off = 16; off; off >>= 1)
                sum += __shfl_xor_sync(0xffffffffu, sum, off);
            if (ln == 0) {
                mrow[r] = mnew;
                lrow[r] = lrow[r] * f + sum;
                frow[r] = f;
            }
        }
        __syncthreads();

        for (int i = tid; i < cn * 32; i += 256) {
            int j = i >> 5, c = (i & 31) * 4;
            float4 v = *(const float4*)(g_qkv + (size_t)(cs + j) * QKVN +
                                        QSIZE + KVSIZE + kvh * HD + c);
            kv[j * AP + c + 0] = to_tf32(v.x);
            kv[j * AP + c + 1] = to_tf32(v.y);
            kv[j * AP + c + 2] = to_tf32(v.z);
            kv[j * AP + c + 3] = to_tf32(v.w);
        }
        for (int i = cn * 32 + tid; i < 128 * 32; i += 256) {
            int j = i >> 5, c = (i & 31) * 4;
            kv[j * AP + c + 0] = 0.f;
            kv[j * AP + c + 1] = 0.f;
            kv[j * AP + c + 2] = 0.f;
            kv[j * AP + c + 3] = 0.f;
        }
        __syncthreads();

        {
            float f0 = frow[row0], f1 = frow[row1];
#pragma unroll
            for (int nf = 0; nf < 4; nf++) {
                o[nf][0] *= f0; o[nf][1] *= f0;
                o[nf][2] *= f1; o[nf][3] *= f1;
            }
        }
#pragma unroll
        for (int ks = 0; ks < 16; ks++) {
            const int k0 = ks * 8;
            uint32_t a[4];
            a[0] = __float_as_uint(sc[row0 * AP + k0 + tig]);
            a[1] = __float_as_uint(sc[row1 * AP + k0 + tig]);
            a[2] = __float_as_uint(sc[row0 * AP + k0 + tig + 4]);
            a[3] = __float_as_uint(sc[row1 * AP + k0 + tig + 4]);
#pragma unroll
            for (int nf = 0; nf < 4; nf++) {
                const int dimc = wn + nf * 8 + grp;
                uint32_t b[2];
                b[0] = __float_as_uint(kv[(k0 + tig)     * AP + dimc]);
                b[1] = __float_as_uint(kv[(k0 + tig + 4) * AP + dimc]);
                mma_tf32(o[nf], a, b);
            }
        }
    }
    __syncthreads();

    // epilogue: normalize, gate, tf32-round (out-proj GEMM input), store
    {
        float g0 = g_gate[(size_t)(t0 + row0) * NH + h] / lrow[row0];
        float g1 = g_gate[(size_t)(t0 + row1) * NH + h] / lrow[row1];
#pragma unroll
        for (int nf = 0; nf < 4; nf++) {
            const int col = wn + nf * 8 + 2 * tig;
            *(float2*)(g_attn + (size_t)(t0 + row0) * QSIZE + h * HD + col) =
                make_float2(to_tf32(o[nf][0] * g0), to_tf32(o[nf][1] * g0));
            *(float2*)(g_attn + (size_t)(t0 + row1) * QSIZE + h * HD + col) =
                make_float2(to_tf32(o[nf][2] * g1), to_tf32(o[nf][3] * g1));
        }
    }
}

// =====================================================================
// launch
// =====================================================================
extern "C" void kernel_launch(void* const* d_in, const int* in_sizes, int n_in,
                              void* d_out, int out_size)
{
    const int*   positions = 0;
    const float* X    = 0;
    const float* Wqkv = 0;
    const float* Wo   = 0;
    const float* Wg   = 0;
    const float* qw   = 0;
    const float* kw   = 0;

    for (int i = 0; i < n_in; i++) {
        switch (in_sizes[i]) {
            case T_TOK:          positions = (const int*)d_in[i];     break;
            case T_TOK*HIDDEN:   X    = (const float*)d_in[i];        break;
            case HIDDEN*QKVN:    Wqkv = (const float*)d_in[i];        break;
            case QSIZE*HIDDEN:   Wo   = (const float*)d_in[i];        break;
            case HIDDEN*NH:      Wg   = (const float*)d_in[i];        break;
            case HD:             if (!qw) qw = (const float*)d_in[i];
                                 else     kw = (const float*)d_in[i]; break;
            default: break;
        }
    }

    float *qkv_p, *attn_p, *xt_p, *wqkvt_p, *wot_p;
    cudaGetSymbolAddress((void**)&qkv_p,   g_qkv);
    cudaGetSymbolAddress((void**)&attn_p,  g_attn);
    cudaGetSymbolAddress((void**)&xt_p,    g_xt);
    cudaGetSymbolAddress((void**)&wqkvt_p, g_wqkvt);
    cudaGetSymbolAddress((void**)&wot_p,   g_wot);
    float* out = (float*)d_out;

    // 0) tf32 pre-conversion of GEMM inputs
    cvt_tf32_k<<<(T_TOK*HIDDEN)/1024, 256>>>(X,    xt_p,    T_TOK*HIDDEN);
    cvt_tf32_k<<<(HIDDEN*QKVN)/1024, 256>>>(Wqkv, wqkvt_p, HIDDEN*QKVN);
    cvt_tf32_k<<<(QSIZE*HIDDEN)/1024, 256>>>(Wo,   wot_p,   QSIZE*HIDDEN);

    // 1) QKV GEMM (cp.async pipelined TF32): [2048,2048] x [2048,6144]
    gemm_tf32_cp<<<dim3(QKVN / 128, T_TOK / 128), 256>>>(xt_p, wqkvt_p, qkv_p,
                                                         T_TOK, QKVN, HIDDEN);
    // 2) RMSNorm + RoPE in place
    norm_rope_k<<<dim3(T_TOK, NH + NKV), 128>>>(positions, qw, kw);
    // 3) Gate
    gate_k<<<T_TOK, 256>>>(X, Wg);
    // 4) Attention (TF32 mma QK + PV, online softmax)
    cudaFuncSetAttribute(attn_k, cudaFuncAttributeMaxDynamicSharedMemorySize,
                         ATTN_SMEM_BYTES);
    attn_k<<<dim3(T_TOK / TQ, NH), 256, ATTN_SMEM_BYTES>>>();
    // 5) Output GEMM (cp.async pipelined TF32): [2048,4096] x [4096,2048]
    gemm_tf32_cp<<<dim3(HIDDEN / 128, T_TOK / 128), 256>>>(attn_p, wot_p, out,
                                                           T_TOK, HIDDEN, QSIZE);
    (void)out_size;
}

// round 17
// speedup vs baseline: 1.1291x; 1.0444x over previous
#include <cuda_runtime.h>
#include <math.h>
#include <stdint.h>

#define T_TOK 2048
#define HIDDEN 2048
#define NH 32
#define NKV 8
#define HD 128
#define QSIZE (NH*HD)              // 4096
#define KVSIZE (NKV*HD)            // 1024
#define QKVN (QSIZE + 2*KVSIZE)    // 6144
#define WINDOW 512
#define TQ 32                      // tokens per block
#define TM 128                     // M rows per block = 4 heads x 32 tokens
#define AP 132                     // attention smem pitch (conflict-free)

// -------- scratch (device globals: allocation-free) --------
__device__ float g_qkv[T_TOK * QKVN];       // 50.3 MB
__device__ float g_gate[T_TOK * NH];        // 0.26 MB
__device__ float g_attn[T_TOK * QSIZE];     // 33.5 MB (tf32-rounded)
__device__ float g_xt[T_TOK * HIDDEN];      // 16.8 MB (X, tf32)
__device__ float g_wqkvt[HIDDEN * QKVN];    // 50.3 MB (Wqkv, tf32)
__device__ float g_wot[QSIZE * HIDDEN];     // 33.5 MB (Wo, tf32)

__device__ __forceinline__ float to_tf32(float x)
{
    uint32_t r;
    asm("cvt.rna.tf32.f32 %0, %1;" : "=r"(r) : "f"(x));
    return __uint_as_float(r);
}

__device__ __forceinline__ void mma_tf32(
    float* d, const uint32_t* a, const uint32_t* b)
{
    asm volatile(
        "mma.sync.aligned.m16n8k8.row.col.f32.tf32.tf32.f32 "
        "{%0,%1,%2,%3}, {%4,%5,%6,%7}, {%8,%9}, {%0,%1,%2,%3};\n"
        : "+f"(d[0]), "+f"(d[1]), "+f"(d[2]), "+f"(d[3])
        : "r"(a[0]), "r"(a[1]), "r"(a[2]), "r"(a[3]),
          "r"(b[0]), "r"(b[1]));
}

#define CP16(saddr, gptr) \
    asm volatile("cp.async.ca.shared.global [%0], [%1], 16;\n" \
                 :: "r"(saddr), "l"(gptr) : "memory")
#define CP_COMMIT() asm volatile("cp.async.commit_group;\n" ::: "memory")
#define CP_WAIT1()  asm volatile("cp.async.wait_group 1;\n" ::: "memory")

// =====================================================================
// tf32 pre-conversion
// =====================================================================
__global__ __launch_bounds__(256) void cvt_tf32_k(
    const float* __restrict__ s, float* __restrict__ d, int n)
{
    int i = (blockIdx.x * 256 + threadIdx.x) * 4;
    if (i < n) {
        float4 v = *(const float4*)(s + i);
        v.x = to_tf32(v.x); v.y = to_tf32(v.y);
        v.z = to_tf32(v.z); v.w = to_tf32(v.w);
        *(float4*)(d + i) = v;
    }
}

// =====================================================================
// TF32 GEMM with cp.async double-buffered pipeline (round-16, unchanged)
// =====================================================================
__global__ __launch_bounds__(256) void gemm_tf32_cp(
    const float* __restrict__ A, const float* __restrict__ B,
    float* __restrict__ C, int M, int N, int K)
{
    __shared__ float As[2][128][20];
    __shared__ float Bs[2][16][136];

    const int m0 = blockIdx.y * 128;
    const int n0 = blockIdx.x * 128;
    const int tid  = threadIdx.x;
    const int wid  = tid >> 5;
    const int lane = tid & 31;
    const int wm = (wid >> 2) * 64;
    const int wn = (wid & 3) * 32;
    const int grp = lane >> 2;
    const int tig = lane & 3;

    float acc[4][4][4];
#pragma unroll
    for (int mf = 0; mf < 4; mf++)
#pragma unroll
        for (int nf = 0; nf < 4; nf++)
#pragma unroll
            for (int r = 0; r < 4; r++) acc[mf][nf][r] = 0.f;

    const int ar = tid >> 1, ac = (tid & 1) * 8;
    const int br = tid >> 4, bc = (tid & 15) * 8;
    const float* gA = A + (size_t)(m0 + ar) * K + ac;
    const float* gB = B + (size_t)br * N + n0 + bc;

    const uint32_t sAme = (uint32_t)__cvta_generic_to_shared(&As[0][ar][ac]);
    const uint32_t sBme = (uint32_t)__cvta_generic_to_shared(&Bs[0][br][bc]);
    const uint32_t ASTG = 128 * 20 * 4;
    const uint32_t BSTG = 16 * 136 * 4;

    const int nt = K / 16;

#define GEMM_ISSUE(tile)                                              \
    do {                                                              \
        const int st_ = (tile) & 1;                                   \
        const float* a_ = gA + (tile) * 16;                           \
        const float* b_ = gB + (size_t)((tile) * 16) * N;             \
        CP16(sAme + st_ * ASTG,      a_);                             \
        CP16(sAme + st_ * ASTG + 16, a_ + 4);                         \
        CP16(sBme + st_ * BSTG,      b_);                             \
        CP16(sBme + st_ * BSTG + 16, b_ + 4);                         \
    } while (0)

    GEMM_ISSUE(0); CP_COMMIT();
    GEMM_ISSUE(1); CP_COMMIT();

    for (int it = 0; it < nt; it++) {
        CP_WAIT1();
        __syncthreads();
        const int st = it & 1;

#pragma unroll
        for (int ks = 0; ks < 16; ks += 8) {
            uint32_t af[4][4], bf[4][2];
#pragma unroll
            for (int mf = 0; mf < 4; mf++) {
                int row = wm + mf * 16 + grp;
                af[mf][0] = __float_as_uint(As[st][row    ][ks + tig]);
                af[mf][1] = __float_as_uint(As[st][row + 8][ks + tig]);
                af[mf][2] = __float_as_uint(As[st][row    ][ks + tig + 4]);
                af[mf][3] = __float_as_uint(As[st][row + 8][ks + tig + 4]);
            }
#pragma unroll
            for (int nf = 0; nf < 4; nf++) {
                int col = wn + nf * 8 + grp;
                bf[nf][0] = __float_as_uint(Bs[st][ks + tig    ][col]);
                bf[nf][1] = __float_as_uint(Bs[st][ks + tig + 4][col]);
            }
#pragma unroll
            for (int mf = 0; mf < 4; mf++)
#pragma unroll
                for (int nf = 0; nf < 4; nf++)
                    mma_tf32(acc[mf][nf], af[mf], bf[nf]);
        }

        __syncthreads();
        if (it + 2 < nt) GEMM_ISSUE(it + 2);
        CP_COMMIT();
    }

#pragma unroll
    for (int mf = 0; mf < 4; mf++) {
        int row = m0 + wm + mf * 16 + grp;
#pragma unroll
        for (int nf = 0; nf < 4; nf++) {
            int col = n0 + wn + nf * 8 + 2 * tig;
            *(float2*)(C + (size_t)row * N + col) =
                make_float2(acc[mf][nf][0], acc[mf][nf][1]);
            *(float2*)(C + (size_t)(row + 8) * N + col) =
                make_float2(acc[mf][nf][2], acc[mf][nf][3]);
        }
    }
#undef GEMM_ISSUE
}

// =====================================================================
// RMSNorm + RoPE in place. sincosf(x, &s, &c): sin FIRST.
// =====================================================================
__global__ __launch_bounds__(128) void norm_rope_k(
    const int* __restrict__ pos,
    const float* __restrict__ qw, const float* __restrict__ kw)
{
    const int t  = blockIdx.x;
    const int hh = blockIdx.y;
    const bool is_q = (hh < NH);
    float* x = g_qkv + (size_t)t * QKVN +
               (is_q ? hh * HD : QSIZE + (hh - NH) * HD);
    const float* w = is_q ? qw : kw;
    const int d = threadIdx.x;

    float v = x[d];
    float ss = v * v;
#pragma unroll
    for (int o = 16; o; o >>= 1) ss += __shfl_xor_sync(0xffffffffu, ss, o);
    __shared__ float red[4];
    if ((d & 31) == 0) red[d >> 5] = ss;
    __syncthreads();
    float r = rsqrtf((red[0] + red[1] + red[2] + red[3]) * (1.0f / HD) + 1e-6f);

    __shared__ float xs[HD];
    xs[d] = v * r * w[d];
    __syncthreads();

    if (d < 64) {
        float inv = powf(10000.0f, -(float)(2 * d) * (1.0f / HD));
        float ang = (float)pos[t] * inv;
        float s, c;
        sincosf(ang, &s, &c);
        float x1 = xs[d], x2 = xs[d + 64];
        x[d]      = x1 * c - x2 * s;
        x[d + 64] = x2 * c + x1 * s;
    }
}

// =====================================================================
// Gate: softplus(X @ Wg). grid T, block 256.
// =====================================================================
__global__ __launch_bounds__(256) void gate_k(
    const float* __restrict__ X, const float* __restrict__ wg)
{
    const int t   = blockIdx.x;
    const int h   = threadIdx.x >> 3;
    const int sub = threadIdx.x & 7;
    const float* xr = X + (size_t)t * HIDDEN;

    float acc = 0.f;
    for (int k = sub; k < HIDDEN; k += 8)
        acc = fmaf(xr[k], wg[(size_t)k * NH + h], acc);
    acc += __shfl_xor_sync(0xffffffffu, acc, 1);
    acc += __shfl_xor_sync(0xffffffffu, acc, 2);
    acc += __shfl_xor_sync(0xffffffffu, acc, 4);
    if (sub == 0) {
        float sp = (acc > 20.f) ? acc : log1pf(expf(acc));
        g_gate[(size_t)t * NH + h] = sp;
    }
}

// =====================================================================
// GQA-BATCHED sliding-window flash attention, TF32 MMA.
// grid (T/32, NKV=8), block 256 (8 warps), 1 CTA/SM (200 KB smem).
// M = 128 rows = 4 q-heads x 32 tokens sharing one kv-head's K/V.
// Row r: head = kvh*4 + (r>>5), token = t0 + (r&31).
// Warp tile 32x64: wm=(wid>>1)*32, wn=(wid&1)*64.
// =====================================================================
#define ATTN_SMEM_FLOATS (3 * TM * AP + 3 * TM)
#define ATTN_SMEM_BYTES  (ATTN_SMEM_FLOATS * 4)

__global__ __launch_bounds__(256, 1) void attn_k()
{
    extern __shared__ float sm[];
    float* qs   = sm;                    // Q  [TM][AP] (tf32, pre-scaled)
    float* kv   = sm + TM * AP;          // K or V [128][AP] natural
    float* sc   = kv + 128 * AP;         // scores / P [TM][AP]
    float* mrow = sc + TM * AP;
    float* lrow = mrow + TM;
    float* frow = lrow + TM;

    const int t0  = blockIdx.x * TQ;
    const int kvh = blockIdx.y;
    const int tid = threadIdx.x;
    const int wid = tid >> 5;
    const int ln  = tid & 31;
    const int wm  = (wid >> 1) * 32;     // 0,32,64,96
    const int wn  = (wid & 1) * 64;      // 0,64
    const int grp = ln >> 2;             // 0..7
    const int tig = ln & 3;              // 0..3

    const int s_min = max(0, t0 - (WINDOW - 1));
    const int s_end = t0 + TQ;
    const float scale = 0.08838834764831845f;  // 128^-0.5

    if (tid < TM) { mrow[tid] = -1e30f; lrow[tid] = 0.f; }
    // Q: row r -> head kvh*4 + (r>>5), token t0 + (r&31)
    for (int i = tid; i < TM * 32; i += 256) {
        int r = i >> 5, c = (i & 31) * 4;
        int hq = kvh * 4 + (r >> 5);
        int t  = t0 + (r & 31);
        float4 v = *(const float4*)(g_qkv + (size_t)t * QKVN + hq * HD + c);
        qs[r * AP + c + 0] = to_tf32(v.x * scale);
        qs[r * AP + c + 1] = to_tf32(v.y * scale);
        qs[r * AP + c + 2] = to_tf32(v.z * scale);
        qs[r * AP + c + 3] = to_tf32(v.w * scale);
    }

    // output accumulators: mf(2) x nf(8) x 4
    float o[2][8][4];
#pragma unroll
    for (int mf = 0; mf < 2; mf++)
#pragma unroll
        for (int nf = 0; nf < 8; nf++)
#pragma unroll
            for (int r = 0; r < 4; r++) o[mf][nf][r] = 0.f;

    for (int cs = s_min; cs < s_end; cs += 128) {
        const int cn = min(128, s_end - cs);
        __syncthreads();   // prev PV done; Q/stats ready

        // ---- load K chunk [key][dim], tf32 ----
        for (int i = tid; i < cn * 32; i += 256) {
            int j = i >> 5, c = (i & 31) * 4;
            float4 v = *(const float4*)(g_qkv + (size_t)(cs + j) * QKVN +
                                        QSIZE + kvh * HD + c);
            kv[j * AP + c + 0] = to_tf32(v.x);
            kv[j * AP + c + 1] = to_tf32(v.y);
            kv[j * AP + c + 2] = to_tf32(v.z);
            kv[j * AP + c + 3] = to_tf32(v.w);
        }
        __syncthreads();

        // ---- QK^T: M=128, N=128 keys, K=128 dims ----
        float acc[2][8][4];
#pragma unroll
        for (int mf = 0; mf < 2; mf++)
#pragma unroll
            for (int nf = 0; nf < 8; nf++)
#pragma unroll
                for (int r = 0; r < 4; r++) acc[mf][nf][r] = 0.f;

#pragma unroll
        for (int ks = 0; ks < 16; ks++) {
            const int k0 = ks * 8;
            uint32_t a[2][4];
#pragma unroll
            for (int mf = 0; mf < 2; mf++) {
                int r0 = wm + mf * 16 + grp;
                a[mf][0] = __float_as_uint(qs[r0 * AP + k0 + tig]);
                a[mf][1] = __float_as_uint(qs[(r0 + 8) * AP + k0 + tig]);
                a[mf][2] = __float_as_uint(qs[r0 * AP + k0 + tig + 4]);
                a[mf][3] = __float_as_uint(qs[(r0 + 8) * AP + k0 + tig + 4]);
            }
#pragma unroll
            for (int nf = 0; nf < 8; nf++) {
                const int key = wn + nf * 8 + grp;
                uint32_t b[2];
                b[0] = __float_as_uint(kv[key * AP + k0 + tig]);
                b[1] = __float_as_uint(kv[key * AP + k0 + tig + 4]);
#pragma unroll
                for (int mf = 0; mf < 2; mf++)
                    mma_tf32(acc[mf][nf], a[mf], b);
            }
        }

        // ---- masked score write ----
#pragma unroll
        for (int mf = 0; mf < 2; mf++) {
            const int r0 = wm + mf * 16 + grp;
            const int tk0 = t0 + (r0 & 31);
            const int tk1 = t0 + ((r0 + 8) & 31);
#pragma unroll
            for (int nf = 0; nf < 8; nf++) {
                const int col = wn + nf * 8 + 2 * tig;
                const int s0 = cs + col, s1 = s0 + 1;
                int d00 = tk0 - s0, d01 = tk0 - s1;
                int d10 = tk1 - s0, d11 = tk1 - s1;
                sc[r0 * AP + col]           = (d00 >= 0 && d00 < WINDOW) ? acc[mf][nf][0] : -1e30f;
                sc[r0 * AP + col + 1]       = (d01 >= 0 && d01 < WINDOW) ? acc[mf][nf][1] : -1e30f;
                sc[(r0 + 8) * AP + col]     = (d10 >= 0 && d10 < WINDOW) ? acc[mf][nf][2] : -1e30f;
                sc[(r0 + 8) * AP + col + 1] = (d11 >= 0 && d11 < WINDOW) ? acc[mf][nf][3] : -1e30f;
            }
        }
        __syncthreads();

        // ---- online softmax (warp per row, 16 rows/warp) ----
        for (int r = wid; r < TM; r += 8) {
            float* row = sc + r * AP;
            float mx = -1e30f;
#pragma unroll 4
            for (int j = ln; j < 128; j += 32) mx = fmaxf(mx, row[j]);
#pragma unroll
            for (int off = 16; off; off >>= 1)
                mx = fmaxf(mx, __shfl_xor_sync(0xffffffffu, mx, off));
            float mold = mrow[r];
            float mnew = fmaxf(mold, mx);
            float f    = expf(mold - mnew);
            float sum  = 0.f;
#pragma unroll 4
            for (int j = ln; j < 128; j += 32) {
                float e = expf(row[j] - mnew);
                row[j] = to_tf32(e);
                sum += e;
            }
#pragma unroll
            for (int off = 16; off; off >>= 1)
                sum += __shfl_xor_sync(0xffffffffu, sum, off);
            if (ln == 0) {
                mrow[r] = mnew;
                lrow[r] = lrow[r] * f + sum;
                frow[r] = f;
            }
        }
        __syncthreads();

        // ---- load V chunk (overwrites K), zero tail keys ----
        for (int i = tid; i < cn * 32; i += 256) {
            int j = i >> 5, c = (i & 31) * 4;
            float4 v = *(const float4*)(g_qkv + (size_t)(cs + j) * QKVN +
                                        QSIZE + KVSIZE + kvh * HD + c);
            kv[j * AP + c + 0] = to_tf32(v.x);
            kv[j * AP + c + 1] = to_tf32(v.y);
            kv[j * AP + c + 2] = to_tf32(v.z);
            kv[j * AP + c + 3] = to_tf32(v.w);
        }
        for (int i = cn * 32 + tid; i < 128 * 32; i += 256) {
            int j = i >> 5, c = (i & 31) * 4;
            kv[j * AP + c + 0] = 0.f;
            kv[j * AP + c + 1] = 0.f;
            kv[j * AP + c + 2] = 0.f;
            kv[j * AP + c + 3] = 0.f;
        }
        __syncthreads();

        // ---- rescale o, then PV: M=128, N=128 dims, K=128 keys ----
#pragma unroll
        for (int mf = 0; mf < 2; mf++) {
            const int r0 = wm + mf * 16 + grp;
            float f0 = frow[r0], f1 = frow[r0 + 8];
#pragma unroll
            for (int nf = 0; nf < 8; nf++) {
                o[mf][nf][0] *= f0; o[mf][nf][1] *= f0;
                o[mf][nf][2] *= f1; o[mf][nf][3] *= f1;
            }
        }
#pragma unroll
        for (int ks = 0; ks < 16; ks++) {
            const int k0 = ks * 8;
            uint32_t a[2][4];
#pragma unroll
            for (int mf = 0; mf < 2; mf++) {
                int r0 = wm + mf * 16 + grp;
                a[mf][0] = __float_as_uint(sc[r0 * AP + k0 + tig]);
                a[mf][1] = __float_as_uint(sc[(r0 + 8) * AP + k0 + tig]);
                a[mf][2] = __float_as_uint(sc[r0 * AP + k0 + tig + 4]);
                a[mf][3] = __float_as_uint(sc[(r0 + 8) * AP + k0 + tig + 4]);
            }
#pragma unroll
            for (int nf = 0; nf < 8; nf++) {
                const int dimc = wn + nf * 8 + grp;
                uint32_t b[2];
                b[0] = __float_as_uint(kv[(k0 + tig)     * AP + dimc]);
                b[1] = __float_as_uint(kv[(k0 + tig + 4) * AP + dimc]);
#pragma unroll
                for (int mf = 0; mf < 2; mf++)
                    mma_tf32(o[mf][nf], a[mf], b);
            }
        }
    }
    __syncthreads();

    // ---- epilogue: normalize, gate, tf32-round, store ----
#pragma unroll
    for (int mf = 0; mf < 2; mf++) {
        const int r0 = wm + mf * 16 + grp;
        const int r1 = r0 + 8;
        const int tk0 = t0 + (r0 & 31), h0 = kvh * 4 + (r0 >> 5);
        const int tk1 = t0 + (r1 & 31), h1 = kvh * 4 + (r1 >> 5);
        float g0 = g_gate[(size_t)tk0 * NH + h0] / lrow[r0];
        float g1 = g_gate[(size_t)tk1 * NH + h1] / lrow[r1];
#pragma unroll
        for (int nf = 0; nf < 8; nf++) {
            const int col = wn + nf * 8 + 2 * tig;
            *(float2*)(g_attn + (size_t)tk0 * QSIZE + h0 * HD + col) =
                make_float2(to_tf32(o[mf][nf][0] * g0), to_tf32(o[mf][nf][1] * g0));
            *(float2*)(g_attn + (size_t)tk1 * QSIZE + h1 * HD + col) =
                make_float2(to_tf32(o[mf][nf][2] * g1), to_tf32(o[mf][nf][3] * g1));
        }
    }
}

// =====================================================================
// launch
// =====================================================================
extern "C" void kernel_launch(void* const* d_in, const int* in_sizes, int n_in,
                              void* d_out, int out_size)
{
    const int*   positions = 0;
    const float* X    = 0;
    const float* Wqkv = 0;
    const float* Wo   = 0;
    const float* Wg   = 0;
    const float* qw   = 0;
    const float* kw   = 0;

    for (int i = 0; i < n_in; i++) {
        switch (in_sizes[i]) {
            case T_TOK:          positions = (const int*)d_in[i];     break;
            case T_TOK*HIDDEN:   X    = (const float*)d_in[i];        break;
            case HIDDEN*QKVN:    Wqkv = (const float*)d_in[i];        break;
            case QSIZE*HIDDEN:   Wo   = (const float*)d_in[i];        break;
            case HIDDEN*NH:      Wg   = (const float*)d_in[i];        break;
            case HD:             if (!qw) qw = (const float*)d_in[i];
                                 else     kw = (const float*)d_in[i]; break;
            default: break;
        }
    }

    float *qkv_p, *attn_p, *xt_p, *wqkvt_p, *wot_p;
    cudaGetSymbolAddress((void**)&qkv_p,   g_qkv);
    cudaGetSymbolAddress((void**)&attn_p,  g_attn);
    cudaGetSymbolAddress((void**)&xt_p,    g_xt);
    cudaGetSymbolAddress((void**)&wqkvt_p, g_wqkvt);
    cudaGetSymbolAddress((void**)&wot_p,   g_wot);
    float* out = (float*)d_out;

    // 0) tf32 pre-conversion of GEMM inputs
    cvt_tf32_k<<<(T_TOK*HIDDEN)/1024, 256>>>(X,    xt_p,    T_TOK*HIDDEN);
    cvt_tf32_k<<<(HIDDEN*QKVN)/1024, 256>>>(Wqkv, wqkvt_p, HIDDEN*QKVN);
    cvt_tf32_k<<<(QSIZE*HIDDEN)/1024, 256>>>(Wo,   wot_p,   QSIZE*HIDDEN);

    // 1) QKV GEMM (cp.async pipelined TF32): [2048,2048] x [2048,6144]
    gemm_tf32_cp<<<dim3(QKVN / 128, T_TOK / 128), 256>>>(xt_p, wqkvt_p, qkv_p,
                                                         T_TOK, QKVN, HIDDEN);
    // 2) RMSNorm + RoPE in place
    norm_rope_k<<<dim3(T_TOK, NH + NKV), 128>>>(positions, qw, kw);
    // 3) Gate
    gate_k<<<T_TOK, 256>>>(X, Wg);
    // 4) GQA-batched flash attention
    cudaFuncSetAttribute(attn_k, cudaFuncAttributeMaxDynamicSharedMemorySize,
                         ATTN_SMEM_BYTES);
    attn_k<<<dim3(T_TOK / TQ, NKV), 256, ATTN_SMEM_BYTES>>>();
    // 5) Output GEMM (cp.async pipelined TF32): [2048,4096] x [4096,2048]
    gemm_tf32_cp<<<dim3(HIDDEN / 128, T_TOK / 128), 256>>>(attn_p, wot_p, out,
                                                           T_TOK, HIDDEN, QSIZE);
    (void)out_size;
}